// round 7
// baseline (speedup 1.0000x reference)
#include <cuda_runtime.h>
#include <math.h>

// Problem constants
#define BB    4        // batch
#define SS    16       // seq len
#define HH    512      // hidden
#define G3    1536     // 3*H
#define CD    256
#define SD    256
#define FLAT  65792    // C*T*F
#define DIN   66304    // CD+SD+FLAT
#define KS    8        // split-K slices over FLAT for the big gemv
#define SLICE (FLAT/KS)    // 8224
#define SLICE4 (SLICE/4)   // 2056 float4s

// Scratch (no allocations allowed -> __device__ globals)
__device__ float g_A[BB*SS*G3];      // per-(b,s) content/style/b_ih contribution to gi
__device__ float g_part[KS*G3*BB];   // split-K partials of W_p @ prev
__device__ float g_gh[BB*G3];        // W_hh @ h
__device__ float g_h[BB*HH];         // recurrent state

// ---------------------------------------------------------------------------
__global__ void k_zero_h() {
    int i = blockIdx.x * blockDim.x + threadIdx.x;
    if (i < BB*HH) g_h[i] = 0.f;
}

// A[bs][r] = b_ih[r] + W_ih[r,0:256]@content[b,s] + W_ih[r,256:512]@style[b]
// grid = G3 blocks, block = 64 threads (one thread per (b,s) pair)
__global__ void k_precompute_A(const float* __restrict__ W_ih,
                               const float* __restrict__ b_ih,
                               const float* __restrict__ content,
                               const float* __restrict__ style) {
    __shared__ float sw[CD + SD];
    int r = blockIdx.x;
    const float* wr = W_ih + (size_t)r * DIN;
    for (int i = threadIdx.x; i < CD + SD; i += 64) sw[i] = wr[i];
    __syncthreads();

    int bs = threadIdx.x;          // 0..63
    int b  = bs >> 4;              // bs / S
    const float* c  = content + (size_t)bs * CD;
    const float* st = style   + (size_t)b  * SD;
    float acc = 0.f;
    #pragma unroll 8
    for (int j = 0; j < CD; j++) acc += sw[j] * c[j];
    #pragma unroll 8
    for (int j = 0; j < SD; j++) acc += sw[CD + j] * st[j];
    g_A[bs * G3 + r] = acc + b_ih[r];
}

// The big one: g_part[sl][r][b] = sum over slice of W_ih[r, 512+j] * x[b][j]
// x[b] = x0 + b*bstride   (bstride=0 broadcasts start_token)
// grid = (G3 rows, KS slices): linear bid order keeps one x-slice L1/L2-hot
// across all 1536 row-blocks of a slice.
__global__ void k_gemv_ih(const float* __restrict__ W_ih,
                          const float* __restrict__ x0, long bstride) {
    int r  = blockIdx.x;
    int sl = blockIdx.y;
    const float4* w4 = (const float4*)(W_ih + (size_t)r * DIN + (CD + SD)) + sl * SLICE4;
    const float4* x4 = (const float4*)(x0) + sl * SLICE4;
    long bs4 = bstride >> 2;

    float a0 = 0.f, a1 = 0.f, a2 = 0.f, a3 = 0.f;
    #pragma unroll 2
    for (int t = threadIdx.x; t < SLICE4; t += 256) {
        float4 w  = w4[t];
        float4 v0 = x4[t];
        float4 v1 = x4[t +     bs4];
        float4 v2 = x4[t + 2 * bs4];
        float4 v3 = x4[t + 3 * bs4];
        a0 += w.x*v0.x + w.y*v0.y + w.z*v0.z + w.w*v0.w;
        a1 += w.x*v1.x + w.y*v1.y + w.z*v1.z + w.w*v1.w;
        a2 += w.x*v2.x + w.y*v2.y + w.z*v2.z + w.w*v2.w;
        a3 += w.x*v3.x + w.y*v3.y + w.z*v3.z + w.w*v3.w;
    }

    __shared__ float red[8][4];
    int lane = threadIdx.x & 31, wid = threadIdx.x >> 5;
    #pragma unroll
    for (int o = 16; o; o >>= 1) {
        a0 += __shfl_down_sync(0xffffffffu, a0, o);
        a1 += __shfl_down_sync(0xffffffffu, a1, o);
        a2 += __shfl_down_sync(0xffffffffu, a2, o);
        a3 += __shfl_down_sync(0xffffffffu, a3, o);
    }
    if (lane == 0) { red[wid][0] = a0; red[wid][1] = a1; red[wid][2] = a2; red[wid][3] = a3; }
    __syncthreads();
    if (threadIdx.x < 4) {
        float s = 0.f;
        #pragma unroll
        for (int w = 0; w < 8; w++) s += red[w][threadIdx.x];
        g_part[(sl * G3 + r) * BB + threadIdx.x] = s;
    }
}

// gh[b][r] = W_hh[r,:] @ h[b]  -- warp per row, grid = G3/8 blocks of 256
__global__ void k_gemv_hh(const float* __restrict__ W_hh) {
    __shared__ float sh[BB*HH];
    for (int i = threadIdx.x; i < BB*HH; i += 256) sh[i] = g_h[i];
    __syncthreads();

    int wid = threadIdx.x >> 5, lane = threadIdx.x & 31;
    int r = blockIdx.x * 8 + wid;
    const float4* w4 = (const float4*)(W_hh + (size_t)r * HH);
    float a[4] = {0.f, 0.f, 0.f, 0.f};
    #pragma unroll
    for (int i = 0; i < 4; i++) {
        int idx = lane + i * 32;               // 0..127 float4s
        float4 w = w4[idx];
        #pragma unroll
        for (int b = 0; b < 4; b++) {
            float4 h = ((const float4*)(sh + b * HH))[idx];
            a[b] += w.x*h.x + w.y*h.y + w.z*h.z + w.w*h.w;
        }
    }
    #pragma unroll
    for (int b = 0; b < 4; b++)
        #pragma unroll
        for (int o = 16; o; o >>= 1) a[b] += __shfl_down_sync(0xffffffffu, a[b], o);
    if (lane == 0) {
        #pragma unroll
        for (int b = 0; b < 4; b++) g_gh[b * G3 + r] = a[b];
    }
}

// Gate update: thread per (b, i<512). PyTorch gate order r,z,n.
__global__ void k_gate(const float* __restrict__ b_hh, int s) {
    int tid = blockIdx.x * blockDim.x + threadIdx.x;   // 0..2047
    int b = tid >> 9, i = tid & 511;
    int bs = b * SS + s;

    float gr = g_A[bs * G3 + i];
    float gz = g_A[bs * G3 + i + HH];
    float gn = g_A[bs * G3 + i + 2*HH];
    #pragma unroll
    for (int k = 0; k < KS; k++) {
        gr += g_part[(k * G3 + i         ) * BB + b];
        gz += g_part[(k * G3 + i + HH    ) * BB + b];
        gn += g_part[(k * G3 + i + 2*HH  ) * BB + b];
    }
    float hr = g_gh[b * G3 + i         ] + b_hh[i];
    float hz = g_gh[b * G3 + i + HH    ] + b_hh[i + HH];
    float hn = g_gh[b * G3 + i + 2*HH  ] + b_hh[i + 2*HH];

    float rg = 1.f / (1.f + expf(-(gr + hr)));
    float zg = 1.f / (1.f + expf(-(gz + hz)));
    float ng = tanhf(gn + rg * hn);
    float hp = g_h[b * HH + i];
    g_h[b * HH + i] = (1.f - zg) * ng + zg * hp;
}

// out[b][s][f] = b_proj[f] + W_proj[f,:] @ h[b] -- warp per row f
__global__ void k_gemv_proj(const float* __restrict__ W_proj,
                            const float* __restrict__ b_proj,
                            float* __restrict__ out, int s) {
    __shared__ float sh[BB*HH];
    for (int i = threadIdx.x; i < BB*HH; i += 256) sh[i] = g_h[i];
    __syncthreads();

    int wid = threadIdx.x >> 5, lane = threadIdx.x & 31;
    int f = blockIdx.x * 8 + wid;
    const float4* w4 = (const float4*)(W_proj + (size_t)f * HH);
    float a[4] = {0.f, 0.f, 0.f, 0.f};
    #pragma unroll
    for (int i = 0; i < 4; i++) {
        int idx = lane + i * 32;
        float4 w = w4[idx];
        #pragma unroll
        for (int b = 0; b < 4; b++) {
            float4 h = ((const float4*)(sh + b * HH))[idx];
            a[b] += w.x*h.x + w.y*h.y + w.z*h.z + w.w*h.w;
        }
    }
    #pragma unroll
    for (int b = 0; b < 4; b++)
        #pragma unroll
        for (int o = 16; o; o >>= 1) a[b] += __shfl_down_sync(0xffffffffu, a[b], o);
    if (lane == 0) {
        float bp = b_proj[f];
        #pragma unroll
        for (int b = 0; b < 4; b++)
            out[((size_t)(b * SS + s)) * FLAT + f] = a[b] + bp;
    }
}

// ---------------------------------------------------------------------------
extern "C" void kernel_launch(void* const* d_in, const int* in_sizes, int n_in,
                              void* d_out, int out_size) {
    const float* content = (const float*)d_in[0];   // (B,S,CD)
    const float* style   = (const float*)d_in[1];   // (B,SD)
    const float* start   = (const float*)d_in[2];   // (FLAT,)
    const float* W_ih    = (const float*)d_in[3];   // (3H, DIN)
    const float* W_hh    = (const float*)d_in[4];   // (3H, H)
    const float* b_ih    = (const float*)d_in[5];
    const float* b_hh    = (const float*)d_in[6];
    const float* W_proj  = (const float*)d_in[7];   // (FLAT, H)
    const float* b_proj  = (const float*)d_in[8];
    float* out = (float*)d_out;                     // (B,S,FLAT) viewed flat

    k_zero_h<<<8, 256>>>();
    k_precompute_A<<<G3, 64>>>(W_ih, b_ih, content, style);

    for (int s = 0; s < SS; s++) {
        const float* x0;
        long bstride;
        if (s == 0) { x0 = start; bstride = 0; }                 // prev0 = start_token (broadcast)
        else { x0 = out + (size_t)(s - 1) * FLAT; bstride = (long)SS * FLAT; }

        k_gemv_ih<<<dim3(G3, KS), 256>>>(W_ih, x0, bstride);     // ~403 MB stream
        k_gemv_hh<<<G3 / 8, 256>>>(W_hh);                        // 3 MB
        k_gate<<<4, 512>>>(b_hh, s);
        k_gemv_proj<<<FLAT / 8, 256>>>(W_proj, b_proj, out, s);  // ~135 MB stream
    }
}

// round 8
// speedup vs baseline: 1.1065x; 1.1065x over previous
#include <cuda_runtime.h>
#include <math.h>

// Problem constants
#define BB    4        // batch
#define SS    16       // seq len
#define HH    512      // hidden
#define G3    1536     // 3*H
#define CD    256
#define SD    256
#define FLAT  65792    // C*T*F
#define DIN   66304    // CD+SD+FLAT
#define KS    32       // split-K slices over FLAT for the big gemv
#define SLICE4 514     // float4s per slice (2056 floats); 32*2056 = 65792

// Scratch (no allocations allowed -> __device__ globals)
__device__ float g_A[BB*SS*G3];      // per-(b,s) content/style/b_ih contribution to gi
__device__ float g_part[KS*G3*BB];   // split-K partials of W_p @ prev
__device__ float g_h[2][BB*HH];      // recurrent state, double-buffered by step parity

// ---------------------------------------------------------------------------
__global__ void k_zero_h() {
    int i = blockIdx.x * blockDim.x + threadIdx.x;
    if (i < BB*HH) g_h[0][i] = 0.f;
}

// A[bs][r] = b_ih[r] + W_ih[r,0:256]@content[b,s] + W_ih[r,256:512]@style[b]
__global__ void k_precompute_A(const float* __restrict__ W_ih,
                               const float* __restrict__ b_ih,
                               const float* __restrict__ content,
                               const float* __restrict__ style) {
    __shared__ float sw[CD + SD];
    int r = blockIdx.x;
    const float* wr = W_ih + (size_t)r * DIN;
    for (int i = threadIdx.x; i < CD + SD; i += 64) sw[i] = wr[i];
    __syncthreads();

    int bs = threadIdx.x;          // 0..63
    int b  = bs >> 4;
    const float* c  = content + (size_t)bs * CD;
    const float* st = style   + (size_t)b  * SD;
    float acc = 0.f;
    #pragma unroll 8
    for (int j = 0; j < CD; j++) acc += sw[j] * c[j];
    #pragma unroll 8
    for (int j = 0; j < SD; j++) acc += sw[CD + j] * st[j];
    g_A[bs * G3 + r] = acc + b_ih[r];
}

// ---------------------------------------------------------------------------
// Big gemv: g_part[sl][r][b] = sum over slice sl of W_ih[r, 512+j] * x[b][j].
// Block = 16 rows x 1 slice; x-slice (4 batches, 32.9 KB) staged in smem so
// W is the only DRAM stream and x L2 traffic drops 16x vs the R3 kernel.
// Each warp owns 2 full rows -> no cross-warp reduction.
__global__ void k_gemv_ih(const float* __restrict__ W_ih,
                          const float* __restrict__ x0, long bstride) {
    __shared__ float4 sx[4][SLICE4];     // 4 * 514 * 16B = 32.9 KB
    int sl = blockIdx.y;

    #pragma unroll
    for (int b = 0; b < 4; b++) {
        const float4* xb = (const float4*)(x0 + (size_t)b * bstride) + (size_t)sl * SLICE4;
        for (int j = threadIdx.x; j < SLICE4; j += 256) sx[b][j] = xb[j];
    }
    __syncthreads();

    int w = threadIdx.x >> 5, lane = threadIdx.x & 31;
    int r0 = blockIdx.x * 16 + w * 2;
    const float4* w0 = (const float4*)(W_ih + (size_t)r0       * DIN + (CD + SD)) + (size_t)sl * SLICE4;
    const float4* w1 = (const float4*)(W_ih + (size_t)(r0 + 1) * DIN + (CD + SD)) + (size_t)sl * SLICE4;

    float a0[4] = {0.f,0.f,0.f,0.f}, a1[4] = {0.f,0.f,0.f,0.f};
    #pragma unroll 4
    for (int j = lane; j < SLICE4; j += 32) {
        float4 u = w0[j], v = w1[j];
        #pragma unroll
        for (int b = 0; b < 4; b++) {
            float4 x = sx[b][j];
            a0[b] += u.x*x.x + u.y*x.y + u.z*x.z + u.w*x.w;
            a1[b] += v.x*x.x + v.y*x.y + v.z*x.z + v.w*x.w;
        }
    }
    #pragma unroll
    for (int b = 0; b < 4; b++) {
        #pragma unroll
        for (int o = 16; o; o >>= 1) {
            a0[b] += __shfl_down_sync(0xffffffffu, a0[b], o);
            a1[b] += __shfl_down_sync(0xffffffffu, a1[b], o);
        }
    }
    if (lane == 0) {
        #pragma unroll
        for (int b = 0; b < 4; b++) {
            g_part[((size_t)sl * G3 + r0    ) * BB + b] = a0[b];
            g_part[((size_t)sl * G3 + r0 + 1) * BB + b] = a1[b];
        }
    }
}

// ---------------------------------------------------------------------------
// Fused W_hh gemv + gate update. Block bx owns hidden indices [bx*32, bx*32+32)
// and computes the 96 W_hh rows (r,z,n gates) it needs, then applies the gate.
// h is double-buffered: phase 1 reads g_h[s&1] (all blocks read the full h),
// phase 2 writes g_h[(s&1)^1] -> no cross-block read/write race.
__global__ void k_hh_gate(const float* __restrict__ W_hh,
                          const float* __restrict__ b_hh, int s) {
    __shared__ float sh[BB*HH];      // h_prev, 8 KB
    __shared__ float sgh[96*4];      // per-(row_local, batch) W_hh dot results
    int rd = s & 1, wr = rd ^ 1;

    for (int t = threadIdx.x; t < BB*HH; t += 256) sh[t] = g_h[rd][t];
    __syncthreads();

    int w = threadIdx.x >> 5, lane = threadIdx.x & 31;
    // 96 local rows -> 12 per warp; each row serves all 4 batches (W loaded once)
    for (int k = 0; k < 12; k++) {
        int rl = w * 12 + k;                              // 0..95
        int r  = (rl >> 5) * HH + blockIdx.x * 32 + (rl & 31);
        const float4* wv = (const float4*)(W_hh + (size_t)r * HH);
        float a[4] = {0.f,0.f,0.f,0.f};
        #pragma unroll
        for (int q = 0; q < 4; q++) {
            float4 ww = wv[lane + q*32];
            #pragma unroll
            for (int b = 0; b < 4; b++) {
                float4 hh = ((const float4*)(sh + b*HH))[lane + q*32];
                a[b] += ww.x*hh.x + ww.y*hh.y + ww.z*hh.z + ww.w*hh.w;
            }
        }
        #pragma unroll
        for (int b = 0; b < 4; b++) {
            #pragma unroll
            for (int o = 16; o; o >>= 1) a[b] += __shfl_down_sync(0xffffffffu, a[b], o);
        }
        if (lane == 0) {
            #pragma unroll
            for (int b = 0; b < 4; b++) sgh[rl*4 + b] = a[b];
        }
    }
    __syncthreads();

    if (threadIdx.x < 128) {
        int b  = threadIdx.x >> 5, il = threadIdx.x & 31;
        int i  = blockIdx.x * 32 + il;
        size_t abase = (size_t)(b * SS + s) * G3 + i;
        float gr = g_A[abase], gz = g_A[abase + HH], gn = g_A[abase + 2*HH];
        #pragma unroll 8
        for (int k2 = 0; k2 < KS; k2++) {
            gr += g_part[((size_t)k2 * G3 + i         ) * BB + b];
            gz += g_part[((size_t)k2 * G3 + i + HH    ) * BB + b];
            gn += g_part[((size_t)k2 * G3 + i + 2*HH  ) * BB + b];
        }
        float hr = sgh[il*4 + b]        + b_hh[i];
        float hz = sgh[(32+il)*4 + b]   + b_hh[i + HH];
        float hn = sgh[(64+il)*4 + b]   + b_hh[i + 2*HH];

        float rg = 1.f / (1.f + expf(-(gr + hr)));
        float zg = 1.f / (1.f + expf(-(gz + hz)));
        float ng = tanhf(gn + rg * hn);
        float hp = sh[b * HH + i];
        g_h[wr][b * HH + i] = (1.f - zg) * ng + zg * hp;
    }
}

// ---------------------------------------------------------------------------
// out[b][s][f] = b_proj[f] + W_proj[f,:] @ h[b]. 2 rows/warp, h in smem.
__global__ void k_gemv_proj(const float* __restrict__ W_proj,
                            const float* __restrict__ b_proj,
                            float* __restrict__ out, int s) {
    __shared__ float sh[BB*HH];
    int wr = (s & 1) ^ 1;            // h written by this step's gate
    for (int t = threadIdx.x; t < BB*HH; t += 256) sh[t] = g_h[wr][t];
    __syncthreads();

    int w = threadIdx.x >> 5, lane = threadIdx.x & 31;
    int f0 = blockIdx.x * 16 + w * 2;
    const float4* p0 = (const float4*)(W_proj + (size_t)f0       * HH);
    const float4* p1 = (const float4*)(W_proj + (size_t)(f0 + 1) * HH);

    float a0[4] = {0.f,0.f,0.f,0.f}, a1[4] = {0.f,0.f,0.f,0.f};
    #pragma unroll
    for (int q = 0; q < 4; q++) {
        float4 u = p0[lane + q*32];
        float4 v = p1[lane + q*32];
        #pragma unroll
        for (int b = 0; b < 4; b++) {
            float4 h = ((const float4*)(sh + b*HH))[lane + q*32];
            a0[b] += u.x*h.x + u.y*h.y + u.z*h.z + u.w*h.w;
            a1[b] += v.x*h.x + v.y*h.y + v.z*h.z + v.w*h.w;
        }
    }
    #pragma unroll
    for (int b = 0; b < 4; b++) {
        #pragma unroll
        for (int o = 16; o; o >>= 1) {
            a0[b] += __shfl_down_sync(0xffffffffu, a0[b], o);
            a1[b] += __shfl_down_sync(0xffffffffu, a1[b], o);
        }
    }
    if (lane == 0) {
        float bp0 = b_proj[f0], bp1 = b_proj[f0 + 1];
        #pragma unroll
        for (int b = 0; b < 4; b++) {
            size_t base = (size_t)(b * SS + s) * FLAT;
            out[base + f0]     = a0[b] + bp0;
            out[base + f0 + 1] = a1[b] + bp1;
        }
    }
}

// ---------------------------------------------------------------------------
extern "C" void kernel_launch(void* const* d_in, const int* in_sizes, int n_in,
                              void* d_out, int out_size) {
    const float* content = (const float*)d_in[0];   // (B,S,CD)
    const float* style   = (const float*)d_in[1];   // (B,SD)
    const float* start   = (const float*)d_in[2];   // (FLAT,)
    const float* W_ih    = (const float*)d_in[3];   // (3H, DIN)
    const float* W_hh    = (const float*)d_in[4];   // (3H, H)
    const float* b_ih    = (const float*)d_in[5];
    const float* b_hh    = (const float*)d_in[6];
    const float* W_proj  = (const float*)d_in[7];   // (FLAT, H)
    const float* b_proj  = (const float*)d_in[8];
    float* out = (float*)d_out;                     // (B,S,FLAT) viewed flat

    k_zero_h<<<8, 256>>>();
    k_precompute_A<<<G3, 64>>>(W_ih, b_ih, content, style);

    for (int s = 0; s < SS; s++) {
        const float* x0;
        long bstride;
        if (s == 0) { x0 = start; bstride = 0; }                 // prev0 = start_token (broadcast)
        else { x0 = out + (size_t)(s - 1) * FLAT; bstride = (long)SS * FLAT; }

        k_gemv_ih<<<dim3(G3/16, KS), 256>>>(W_ih, x0, bstride);  // ~403 MB DRAM stream
        k_hh_gate<<<HH/32, 256>>>(W_hh, b_hh, s);                // fused hh-gemv + gate
        k_gemv_proj<<<FLAT/16, 256>>>(W_proj, b_proj, out, s);   // ~135 MB stream
    }
}